// round 12
// baseline (speedup 1.0000x reference)
#include <cuda_runtime.h>
#include <cuda_bf16.h>
#include <cstdint>
#include <cstddef>

// Problem constants
#define BB 4
#define SS 2048
#define DD 1024
#define HH 16
#define DK 64
#define MM (BB * SS)   // 8192

// Scratch: bf16 hi/lo split inputs + weights
__device__ __nv_bfloat16 g_qhi[(size_t)MM * DD], g_qlo[(size_t)MM * DD];
__device__ __nv_bfloat16 g_khi[(size_t)MM * DD], g_klo[(size_t)MM * DD];
__device__ __nv_bfloat16 g_vhi[(size_t)MM * DD], g_vlo[(size_t)MM * DD];
__device__ __nv_bfloat16 g_Wqhi[DD * DD], g_Wqlo[DD * DD];
__device__ __nv_bfloat16 g_Wkhi[DD * DD], g_Wklo[DD * DD];
__device__ __nv_bfloat16 g_Wvhi[DD * DD], g_Wvlo[DD * DD];
__device__ __nv_bfloat16 g_Wohi[DD * DD], g_Wolo[DD * DD];
// Attention operands (fp32 tf32-rounded) and O split output
__device__ float g_Qh[(size_t)MM * DD];   // [B,H,S,DK] pre-scaled 1/8 via Wq
__device__ float g_Kh[(size_t)MM * DD];   // [B,H,S,DK]
__device__ float g_Vt[(size_t)MM * DD];   // [B,H,DK,S]
__device__ __nv_bfloat16 g_Ohh[(size_t)MM * DD], g_Ohl[(size_t)MM * DD];  // [B,H,S,DK]

// ---------------------------------------------------------------------------
// Helpers
// ---------------------------------------------------------------------------
__device__ __forceinline__ uint32_t smem_u32(const void* p) {
    uint32_t a;
    asm("{ .reg .u64 t; cvta.to.shared.u64 t, %1; cvt.u32.u64 %0, t; }"
        : "=r"(a) : "l"(p));
    return a;
}
__device__ __forceinline__ void cp16(uint32_t saddr, const void* gptr) {
    asm volatile("cp.async.ca.shared.global [%0], [%1], 16;"
                 :: "r"(saddr), "l"(gptr) : "memory");
}
__device__ __forceinline__ void cp_commit() {
    asm volatile("cp.async.commit_group;" ::: "memory");
}
template <int N>
__device__ __forceinline__ void cp_wait() {
    asm volatile("cp.async.wait_group %0;" :: "n"(N) : "memory");
}
__device__ __forceinline__ uint32_t f2tf(float x) {
    uint32_t u;
    asm("cvt.rna.tf32.f32 %0, %1;" : "=r"(u) : "f"(x));
    return u;
}
__device__ __forceinline__ void mma_tf32(float* d, const uint32_t* a, const uint32_t* b) {
    asm volatile(
        "mma.sync.aligned.m16n8k8.row.col.f32.tf32.tf32.f32 "
        "{%0,%1,%2,%3}, {%4,%5,%6,%7}, {%8,%9}, {%0,%1,%2,%3};"
        : "+f"(d[0]), "+f"(d[1]), "+f"(d[2]), "+f"(d[3])
        : "r"(a[0]), "r"(a[1]), "r"(a[2]), "r"(a[3]), "r"(b[0]), "r"(b[1]));
}
__device__ __forceinline__ void mma_bf16(float* d, const uint32_t* a, const uint32_t* b) {
    asm volatile(
        "mma.sync.aligned.m16n8k16.row.col.f32.bf16.bf16.f32 "
        "{%0,%1,%2,%3}, {%4,%5,%6,%7}, {%8,%9}, {%0,%1,%2,%3};"
        : "+f"(d[0]), "+f"(d[1]), "+f"(d[2]), "+f"(d[3])
        : "r"(a[0]), "r"(a[1]), "r"(a[2]), "r"(a[3]), "r"(b[0]), "r"(b[1]));
}
__device__ __forceinline__ void ldsm4(uint32_t* r, uint32_t addr) {
    asm volatile("ldmatrix.sync.aligned.m8n8.x4.shared.b16 {%0,%1,%2,%3}, [%4];"
                 : "=r"(r[0]), "=r"(r[1]), "=r"(r[2]), "=r"(r[3]) : "r"(addr));
}

// ---------------------------------------------------------------------------
// Pre-pass: bf16 hi/lo split of all 7 inputs. grid (8192, 7).
// ---------------------------------------------------------------------------
#define NBIG4 ((int)((size_t)MM * DD / 4))   // 2097152
#define NW4 (DD * DD / 4)                    // 262144

__global__ __launch_bounds__(256)
void split_all(const float4* __restrict__ q, const float4* __restrict__ k,
               const float4* __restrict__ v, const float4* __restrict__ Wq,
               const float4* __restrict__ Wk, const float4* __restrict__ Wv,
               const float4* __restrict__ Wo)
{
    const int y = blockIdx.y;
    const int i = blockIdx.x * blockDim.x + threadIdx.x;
    const float4* src;
    __nv_bfloat16 *dh, *dl;
    int n4;
    float scale = 1.0f;
    switch (y) {
        case 0: src = q;  dh = g_qhi;  dl = g_qlo;  n4 = NBIG4; break;
        case 1: src = k;  dh = g_khi;  dl = g_klo;  n4 = NBIG4; break;
        case 2: src = v;  dh = g_vhi;  dl = g_vlo;  n4 = NBIG4; break;
        case 3: src = Wq; dh = g_Wqhi; dl = g_Wqlo; n4 = NW4; scale = 0.125f; break;
        case 4: src = Wk; dh = g_Wkhi; dl = g_Wklo; n4 = NW4; break;
        case 5: src = Wv; dh = g_Wvhi; dl = g_Wvlo; n4 = NW4; break;
        default: src = Wo; dh = g_Wohi; dl = g_Wolo; n4 = NW4; break;
    }
    if (i < n4) {
        float4 x = src[i];
        x.x *= scale; x.y *= scale; x.z *= scale; x.w *= scale;
        __nv_bfloat16 h0 = __float2bfloat16(x.x);
        __nv_bfloat16 h1 = __float2bfloat16(x.y);
        __nv_bfloat16 h2 = __float2bfloat16(x.z);
        __nv_bfloat16 h3 = __float2bfloat16(x.w);
        __nv_bfloat16 l0 = __float2bfloat16(x.x - __bfloat162float(h0));
        __nv_bfloat16 l1 = __float2bfloat16(x.y - __bfloat162float(h1));
        __nv_bfloat16 l2 = __float2bfloat16(x.z - __bfloat162float(h2));
        __nv_bfloat16 l3 = __float2bfloat16(x.w - __bfloat162float(h3));
        __nv_bfloat162 hh0; hh0.x = h0; hh0.y = h1;
        __nv_bfloat162 hh1; hh1.x = h2; hh1.y = h3;
        __nv_bfloat162 ll0; ll0.x = l0; ll0.y = l1;
        __nv_bfloat162 ll1; ll1.x = l2; ll1.y = l3;
        *(__nv_bfloat162*)&dh[(size_t)i * 4]     = hh0;
        *(__nv_bfloat162*)&dh[(size_t)i * 4 + 2] = hh1;
        *(__nv_bfloat162*)&dl[(size_t)i * 4]     = ll0;
        *(__nv_bfloat162*)&dl[(size_t)i * 4 + 2] = ll1;
    }
}

// ---------------------------------------------------------------------------
// bf16-split GEMM core: C = A @ W^T with A,W as bf16 hi/lo pairs.
// Tile 128x128, BK=32, 256 threads (8 warps of 64x32). 2-stage cp.async.
// Per k16: Ahi*(Bhi+Blo) + Alo*Bhi (lo*lo dropped, ~2^-18 relative).
// ---------------------------------------------------------------------------
#define RH 40                           // halves per smem row (32 + pad 8)
#define TILEH (128 * RH)                // 5120 halves = 10240 bytes per tile
#define TILEB (TILEH * 2)
#define BUFB (4 * TILEB)                // Ahi, Alo, Bhi, Blo = 40960 bytes
#define GSMEM (2 * BUFB)                // 81920 bytes
#define NCHUNK (DD / 32)                // 32

template <bool GATHER>
__device__ __forceinline__ void issue_chunk(uint32_t sbuf, int it,
                                            const __nv_bfloat16* __restrict__ Ahi,
                                            const __nv_bfloat16* __restrict__ Alo,
                                            const __nv_bfloat16* __restrict__ Whi,
                                            const __nv_bfloat16* __restrict__ Wlo,
                                            int bm, int bn, int tid)
{
    const int k0 = it * 32;
    #pragma unroll
    for (int i = 0; i < 2; i++) {
        const int idx = i * 256 + tid;       // 0..511 slots (8-half units)
        const int r = idx >> 2;              // 0..127 tile row
        const int c8 = idx & 3;              // 8-half slot along k
        const int gk = k0 + c8 * 8;
        size_t aoff;
        if (GATHER) {
            const int gm = bm + r;
            const int b = gm >> 11;
            const int s = gm & (SS - 1);
            const int h = gk >> 6;
            const int dk = gk & (DK - 1);
            aoff = ((((size_t)b * HH + h) * SS + s) << 6) + dk;
        } else {
            aoff = (size_t)(bm + r) * DD + gk;
        }
        const size_t woff = (size_t)(bn + r) * DD + gk;
        const uint32_t soff = (uint32_t)(r * RH + c8 * 8) * 2u;
        cp16(sbuf + soff, &Ahi[aoff]);                       // A hi
        cp16(sbuf + TILEB + soff, &Alo[aoff]);               // A lo
        cp16(sbuf + 2 * TILEB + soff, &Whi[woff]);           // B hi
        cp16(sbuf + 3 * TILEB + soff, &Wlo[woff]);           // B lo
    }
    cp_commit();
}

template <bool GATHER>
__device__ __forceinline__ void gemm_core(const __nv_bfloat16* __restrict__ Ahi,
                                          const __nv_bfloat16* __restrict__ Alo,
                                          const __nv_bfloat16* __restrict__ Whi,
                                          const __nv_bfloat16* __restrict__ Wlo,
                                          float (&acc)[4][4][4],
                                          int bm, int bn, char* smem)
{
    const uint32_t sb = smem_u32(smem);
    const int tid = threadIdx.x;
    const int lane = tid & 31;
    const int wid = tid >> 5;
    const int wm = wid >> 2;        // 0..1  (64-row slab)
    const int wn = wid & 3;         // 0..3  (32-col slab)

    // b16 ldmatrix per-lane address: rows = lane&15, col-halves offset = (lane>>4)*8
    const uint32_t lrow = (uint32_t)(lane & 15);
    const uint32_t lcol = (uint32_t)(lane >> 4) * 8u;
    const uint32_t aoff = ((wm * 64 + lrow) * RH + lcol) * 2u;
    const uint32_t boff = ((wn * 32 + lrow) * RH + lcol) * 2u;

    const uint32_t sbuf[2] = { sb, sb + (uint32_t)BUFB };

    issue_chunk<GATHER>(sbuf[0], 0, Ahi, Alo, Whi, Wlo, bm, bn, tid);

    for (int it = 0; it < NCHUNK; ++it) {
        const int cur = it & 1;
        if (it + 1 < NCHUNK) {
            issue_chunk<GATHER>(sbuf[cur ^ 1], it + 1, Ahi, Alo, Whi, Wlo, bm, bn, tid);
            cp_wait<1>();
        } else {
            cp_wait<0>();
        }
        __syncthreads();

        const uint32_t aTh = sbuf[cur] + aoff;
        const uint32_t aTl = sbuf[cur] + TILEB + aoff;
        const uint32_t bTh = sbuf[cur] + 2 * TILEB + boff;
        const uint32_t bTl = sbuf[cur] + 3 * TILEB + boff;

        #pragma unroll
        for (int ks = 0; ks < 2; ks++) {        // two k16 steps per 32-chunk
            const uint32_t koff = (uint32_t)ks * 32u;   // 16 halves
            uint32_t bh[4][2], bl[4][2], af[4][4];
            #pragma unroll
            for (int p = 0; p < 2; p++) {
                uint32_t r4[4];
                ldsm4(r4, bTh + (uint32_t)(p * 16 * RH) * 2u + koff);
                bh[2 * p][0] = r4[0]; bh[2 * p][1] = r4[2];
                bh[2 * p + 1][0] = r4[1]; bh[2 * p + 1][1] = r4[3];
                ldsm4(r4, bTl + (uint32_t)(p * 16 * RH) * 2u + koff);
                bl[2 * p][0] = r4[0]; bl[2 * p][1] = r4[2];
                bl[2 * p + 1][0] = r4[1]; bl[2 * p + 1][1] = r4[3];
            }
            #pragma unroll
            for (int mt = 0; mt < 4; mt++)
                ldsm4(af[mt], aTh + (uint32_t)(mt * 16 * RH) * 2u + koff);
            #pragma unroll
            for (int mt = 0; mt < 4; mt++)
                #pragma unroll
                for (int nt = 0; nt < 4; nt++) {
                    mma_bf16(acc[mt][nt], af[mt], bh[nt]);   // hi*hi
                    mma_bf16(acc[mt][nt], af[mt], bl[nt]);   // hi*lo
                }
            #pragma unroll
            for (int mt = 0; mt < 4; mt++)
                ldsm4(af[mt], aTl + (uint32_t)(mt * 16 * RH) * 2u + koff);
            #pragma unroll
            for (int mt = 0; mt < 4; mt++)
                #pragma unroll
                for (int nt = 0; nt < 4; nt++)
                    mma_bf16(acc[mt][nt], af[mt], bh[nt]);   // lo*hi
        }
        __syncthreads();
    }
}

// Fused Q/K/V projections: grid (8, 64, 3). z=0 -> Qh, z=1 -> Kh, z=2 -> Vt.
__global__ __launch_bounds__(256, 2)
void gemm_qkv(float* __restrict__ C0, float* __restrict__ C1, float* __restrict__ C2)
{
    extern __shared__ char smem[];
    const int z = blockIdx.z;
    const __nv_bfloat16 *Ahi, *Alo, *Whi, *Wlo;
    float* C;
    if (z == 0) { Ahi = g_qhi; Alo = g_qlo; Whi = g_Wqhi; Wlo = g_Wqlo; C = C0; }
    else if (z == 1) { Ahi = g_khi; Alo = g_klo; Whi = g_Wkhi; Wlo = g_Wklo; C = C1; }
    else { Ahi = g_vhi; Alo = g_vlo; Whi = g_Wvhi; Wlo = g_Wvlo; C = C2; }
    const int bm = blockIdx.y * 128;
    const int bn = blockIdx.x * 128;

    float acc[4][4][4];
    #pragma unroll
    for (int i = 0; i < 4; i++)
        #pragma unroll
        for (int j = 0; j < 4; j++)
            #pragma unroll
            for (int r = 0; r < 4; r++) acc[i][j][r] = 0.f;

    gemm_core<false>(Ahi, Alo, Whi, Wlo, acc, bm, bn, smem);

    const int lane = threadIdx.x & 31;
    const int wid = threadIdx.x >> 5;
    const int g = lane >> 2;
    const int tig = lane & 3;
    const int wm = wid >> 2;
    const int wn = wid & 3;

    #pragma unroll
    for (int mt = 0; mt < 4; mt++) {
        #pragma unroll
        for (int half = 0; half < 2; half++) {
            const int gm = bm + wm * 64 + mt * 16 + g + half * 8;
            const int b = gm >> 11;
            const int s = gm & (SS - 1);
            #pragma unroll
            for (int nt = 0; nt < 4; nt++) {
                const int gn = bn + wn * 32 + nt * 8 + 2 * tig;
                const float vx = __uint_as_float(f2tf(acc[mt][nt][half * 2 + 0]));
                const float vy = __uint_as_float(f2tf(acc[mt][nt][half * 2 + 1]));
                const int h = gn >> 6;
                const int dk = gn & (DK - 1);
                if (z < 2) {
                    float2 o; o.x = vx; o.y = vy;
                    *(float2*)&C[((((size_t)b * HH + h) * SS + s) << 6) + dk] = o;
                } else {
                    const size_t base = (((size_t)b * HH + h) * DK);
                    C[(base + dk) * SS + s] = vx;
                    C[(base + dk + 1) * SS + s] = vy;
                }
            }
        }
    }
}

// Output projection: A = O (head-split bf16 hi/lo), plain fp32 epilogue.
__global__ __launch_bounds__(256, 2)
void gemm_o(float* __restrict__ C)
{
    extern __shared__ char smem[];
    const int bm = blockIdx.y * 128;
    const int bn = blockIdx.x * 128;

    float acc[4][4][4];
    #pragma unroll
    for (int i = 0; i < 4; i++)
        #pragma unroll
        for (int j = 0; j < 4; j++)
            #pragma unroll
            for (int r = 0; r < 4; r++) acc[i][j][r] = 0.f;

    gemm_core<true>(g_Ohh, g_Ohl, g_Wohi, g_Wolo, acc, bm, bn, smem);

    const int lane = threadIdx.x & 31;
    const int wid = threadIdx.x >> 5;
    const int g = lane >> 2;
    const int tig = lane & 3;
    const int wm = wid >> 2;
    const int wn = wid & 3;

    #pragma unroll
    for (int mt = 0; mt < 4; mt++) {
        #pragma unroll
        for (int half = 0; half < 2; half++) {
            const int gm = bm + wm * 64 + mt * 16 + g + half * 8;
            #pragma unroll
            for (int nt = 0; nt < 4; nt++) {
                const int gn = bn + wn * 32 + nt * 8 + 2 * tig;
                float2 o;
                o.x = acc[mt][nt][half * 2 + 0];
                o.y = acc[mt][nt][half * 2 + 1];
                *(float2*)&C[(size_t)gm * DD + gn] = o;
            }
        }
    }
}

// ---------------------------------------------------------------------------
// Tensorized causal flash attention (R9 core, tf32; O written as bf16 hi/lo).
// Qh (pre-scaled)/Kh [B,H,S,DK] fp32-tf32; Vt [B,H,DK,S] fp32-tf32.
// CTA = 128 queries, 128 threads (each warp: 32 queries = 2 m16 groups).
// ---------------------------------------------------------------------------
#define QT 128
#define AST 68
#define ATILE (64 * AST)
#define ASMEM (4 * ATILE * 4)          // 69632 bytes

__device__ __forceinline__ void attn_stage(uint32_t sK, uint32_t sV,
                                           const float* __restrict__ Kh,
                                           const float* __restrict__ Vt,
                                           size_t headoff, int kb, int tid)
{
    #pragma unroll
    for (int i = 0; i < 8; i++) {
        const int idx = i * 128 + tid;
        const int r = idx >> 4;
        const int c4 = idx & 15;
        const uint32_t soff = (uint32_t)(r * AST + c4 * 4) * 4u;
        cp16(sK + soff, &Kh[headoff + (size_t)(kb * 64 + r) * DK + c4 * 4]);
        cp16(sV + soff, &Vt[headoff + (size_t)r * SS + kb * 64 + c4 * 4]);
    }
    cp_commit();
}

__global__ __launch_bounds__(128, 2)
void attn_mma(const float* __restrict__ Qh, const float* __restrict__ Kh,
              const float* __restrict__ Vt)
{
    extern __shared__ float sm[];
    const uint32_t sb = smem_u32(sm);
    const uint32_t sK[2] = { sb, sb + (uint32_t)ATILE * 4u };
    const uint32_t sV[2] = { sb + 2u * ATILE * 4u, sb + 3u * ATILE * 4u };

    const int tid = threadIdx.x;
    const int wid = tid >> 5;
    const int lane = tid & 31;
    const int g = lane >> 2;
    const int tig = lane & 3;
    const int tr = lane & 7;
    const int qd = lane >> 3;
    const int qt = gridDim.x - 1 - blockIdx.x;   // heavy tiles first
    const int h = blockIdx.y;
    const int b = blockIdx.z;
    const size_t headoff = ((size_t)(b * HH + h)) * SS * DK;
    const int nkb = 2 * qt + 2;

    // Stage 128 Q rows across the contiguous sK[0]|sK[1] region (stride AST).
    #pragma unroll
    for (int i = 0; i < 16; i++) {
        const int idx = i * 128 + tid;
        const int r = idx >> 4;
        const int c4 = idx & 15;
        cp16(sK[0] + (uint32_t)(r * AST + c4 * 4) * 4u,
             &Qh[headoff + (size_t)(qt * QT + r) * DK + c4 * 4]);
    }
    cp_commit();
    cp_wait<0>();
    __syncthreads();

    // Q fragments for both 16-row groups of this warp's 32 queries.
    uint32_t qf[2][8][4];
    #pragma unroll
    for (int grp = 0; grp < 2; grp++) {
        const uint32_t qbase = sK[0]
            + (uint32_t)((wid * 32 + grp * 16 + (qd & 1) * 8 + tr) * AST + (qd >> 1) * 4) * 4u;
        #pragma unroll
        for (int ks = 0; ks < 8; ks++)
            ldsm4(qf[grp][ks], qbase + (uint32_t)ks * 32u);
    }
    __syncthreads();

    // Stage kb=0 K/V into buf 0.
    attn_stage(sK[0], sV[0], Kh, Vt, headoff, 0, tid);

    const uint32_t foff = (uint32_t)(((qd >> 1) * 8 + tr) * AST + (qd & 1) * 4) * 4u;

    float oacc[2][8][4];
    #pragma unroll
    for (int grp = 0; grp < 2; grp++)
        #pragma unroll
        for (int nt = 0; nt < 8; nt++)
            #pragma unroll
            for (int r = 0; r < 4; r++) oacc[grp][nt][r] = 0.f;
    float m[2][2] = { {-1e30f, -1e30f}, {-1e30f, -1e30f} };
    float l[2][2] = { {0.f, 0.f}, {0.f, 0.f} };

    const int base = (lane & ~3) | (tig >> 1);
    const bool odd = tig & 1;

    for (int kb = 0; kb < nkb; kb++) {
        const int cur = kb & 1;
        if (kb + 1 < nkb) {
            attn_stage(sK[cur ^ 1], sV[cur ^ 1], Kh, Vt, headoff, kb + 1, tid);
            cp_wait<1>();
        } else {
            cp_wait<0>();
        }
        __syncthreads();

        // ---- S = Q K^T for both groups (shared K fragments) ----
        float sacc[2][8][4];
        #pragma unroll
        for (int grp = 0; grp < 2; grp++)
            #pragma unroll
            for (int nt = 0; nt < 8; nt++)
                #pragma unroll
                for (int r = 0; r < 4; r++) sacc[grp][nt][r] = 0.f;

        const uint32_t kT = sK[cur] + foff;
        #pragma unroll
        for (int ks = 0; ks < 8; ks++) {
            uint32_t bfr[8][2];
            #pragma unroll
            for (int p = 0; p < 4; p++) {
                uint32_t r4[4];
                ldsm4(r4, kT + (uint32_t)(p * 16 * AST) * 4u + (uint32_t)ks * 32u);
                bfr[2 * p][0] = r4[0]; bfr[2 * p][1] = r4[1];
                bfr[2 * p + 1][0] = r4[2]; bfr[2 * p + 1][1] = r4[3];
            }
            #pragma unroll
            for (int grp = 0; grp < 2; grp++)
                #pragma unroll
                for (int nt = 0; nt < 8; nt++)
                    mma_tf32(sacc[grp][nt], qf[grp][ks], bfr[nt]);
        }

        // ---- causal mask (last two k-blocks only) ----
        const int rel = (kb - 2 * qt) * 64;
        if (rel >= 0) {
            #pragma unroll
            for (int grp = 0; grp < 2; grp++) {
                const int ql0 = wid * 32 + grp * 16 + g;
                const int ql1 = ql0 + 8;
                #pragma unroll
                for (int nt = 0; nt < 8; nt++) {
                    const int kc = rel + nt * 8 + 2 * tig;
                    if (kc > ql0)     sacc[grp][nt][0] = -1e30f;
                    if (kc + 1 > ql0) sacc[grp][nt][1] = -1e30f;
                    if (kc > ql1)     sacc[grp][nt][2] = -1e30f;
                    if (kc + 1 > ql1) sacc[grp][nt][3] = -1e30f;
                }
            }
        }

        // ---- online softmax bookkeeping per group ----
        float nm[2][2];
        #pragma unroll
        for (int grp = 0; grp < 2; grp++) {
            float tmax0 = -1e30f, tmax1 = -1e30f;
            #pragma unroll
            for (int nt = 0; nt < 8; nt++) {
                tmax0 = fmaxf(tmax0, fmaxf(sacc[grp][nt][0], sacc[grp][nt][1]));
                tmax1 = fmaxf(tmax1, fmaxf(sacc[grp][nt][2], sacc[grp][nt][3]));
            }
            tmax0 = fmaxf(tmax0, __shfl_xor_sync(0xffffffffu, tmax0, 1));
            tmax0 = fmaxf(tmax0, __shfl_xor_sync(0xffffffffu, tmax0, 2));
            tmax1 = fmaxf(tmax1, __shfl_xor_sync(0xffffffffu, tmax1, 1));
            tmax1 = fmaxf(tmax1, __shfl_xor_sync(0xffffffffu, tmax1, 2));
            const float nm0 = fmaxf(m[grp][0], tmax0);
            const float nm1 = fmaxf(m[grp][1], tmax1);
            const float corr0 = __expf(m[grp][0] - nm0);
            const float corr1 = __expf(m[grp][1] - nm1);
            l[grp][0] *= corr0;
            l[grp][1] *= corr1;
            #pragma unroll
            for (int nt = 0; nt < 8; nt++) {
                oacc[grp][nt][0] *= corr0; oacc[grp][nt][1] *= corr0;
                oacc[grp][nt][2] *= corr1; oacc[grp][nt][3] *= corr1;
            }
            m[grp][0] = nm0; m[grp][1] = nm1;
            nm[grp][0] = nm0; nm[grp][1] = nm1;
        }

        // ---- PV: shfl-transpose S, exp, mma (shared V fragments) ----
        const uint32_t vT = sV[cur] + foff;
        #pragma unroll
        for (int ks = 0; ks < 8; ks++) {
            uint32_t bfr[8][2];
            #pragma unroll
            for (int p = 0; p < 4; p++) {
                uint32_t r4[4];
                ldsm4(r4, vT + (uint32_t)(p * 16 * AST) * 4u + (uint32_t)ks * 32u);
                bfr[2 * p][0] = r4[0]; bfr[2 * p][1] = r4[1];
                bfr[2 * p + 1][0] = r4[2]; bfr[2 * p + 1][1] = r4[3];
            }
            #pragma unroll
            for (int grp = 0; grp < 2; grp++) {
                const float s00 = __shfl_sync(0xffffffffu, sacc[grp][ks][0], base);
                const float s01 = __shfl_sync(0xffffffffu, sacc[grp][ks][1], base);
                const float s10 = __shfl_sync(0xffffffffu, sacc[grp][ks][2], base);
                const float s11 = __shfl_sync(0xffffffffu, sacc[grp][ks][3], base);
                const float t00 = __shfl_sync(0xffffffffu, sacc[grp][ks][0], base + 2);
                const float t01 = __shfl_sync(0xffffffffu, sacc[grp][ks][1], base + 2);
                const float t10 = __shfl_sync(0xffffffffu, sacc[grp][ks][2], base + 2);
                const float t11 = __shfl_sync(0xffffffffu, sacc[grp][ks][3], base + 2);
                const float p0 = __expf((odd ? s01 : s00) - nm[grp][0]);
                const float p1 = __expf((odd ? s11 : s10) - nm[grp][1]);
                const float p2 = __expf((odd ? t01 : t00) - nm[grp][0]);
                const float p3 = __expf((odd ? t11 : t10) - nm[grp][1]);
                l[grp][0] += p0 + p2;
                l[grp][1] += p1 + p3;
                uint32_t af[4] = { f2tf(p0), f2tf(p1), f2tf(p2), f2tf(p3) };
                #pragma unroll
                for (int nt = 0; nt < 8; nt++)
                    mma_tf32(oacc[grp][nt], af, bfr[nt]);
            }
        }
        __syncthreads();
    }

    // Epilogue: write O as bf16 hi/lo pairs (consumed by gemm_o natively).
    #pragma unroll
    for (int grp = 0; grp < 2; grp++) {
        float la = l[grp][0], lb = l[grp][1];
        la += __shfl_xor_sync(0xffffffffu, la, 1);
        la += __shfl_xor_sync(0xffffffffu, la, 2);
        lb += __shfl_xor_sync(0xffffffffu, lb, 1);
        lb += __shfl_xor_sync(0xffffffffu, lb, 2);
        const float inv0 = 1.f / la;
        const float inv1 = 1.f / lb;
        const int qr0 = qt * QT + wid * 32 + grp * 16 + g;
        const int qr1 = qr0 + 8;
        #pragma unroll
        for (int nt = 0; nt < 8; nt++) {
            const int d = nt * 8 + 2 * tig;
            const float o0x = oacc[grp][nt][0] * inv0;
            const float o0y = oacc[grp][nt][1] * inv0;
            const float o1x = oacc[grp][nt][2] * inv1;
            const float o1y = oacc[grp][nt][3] * inv1;
            __nv_bfloat162 h0, h1, l0_, l1_;
            h0.x = __float2bfloat16(o0x); h0.y = __float2bfloat16(o0y);
            h1.x = __float2bfloat16(o1x); h1.y = __float2bfloat16(o1y);
            l0_.x = __float2bfloat16(o0x - __bfloat162float(h0.x));
            l0_.y = __float2bfloat16(o0y - __bfloat162float(h0.y));
            l1_.x = __float2bfloat16(o1x - __bfloat162float(h1.x));
            l1_.y = __float2bfloat16(o1y - __bfloat162float(h1.y));
            const size_t off0 = headoff + (size_t)qr0 * DK + d;
            const size_t off1 = headoff + (size_t)qr1 * DK + d;
            *(__nv_bfloat162*)&g_Ohh[off0] = h0;
            *(__nv_bfloat162*)&g_Ohh[off1] = h1;
            *(__nv_bfloat162*)&g_Ohl[off0] = l0_;
            *(__nv_bfloat162*)&g_Ohl[off1] = l1_;
        }
    }
}

// ---------------------------------------------------------------------------
extern "C" void kernel_launch(void* const* d_in, const int* in_sizes, int n_in,
                              void* d_out, int out_size)
{
    const float* q  = (const float*)d_in[0];
    const float* k  = (const float*)d_in[1];
    const float* v  = (const float*)d_in[2];
    const float* Wq = (const float*)d_in[3];
    const float* Wk = (const float*)d_in[4];
    const float* Wv = (const float*)d_in[5];
    const float* Wo = (const float*)d_in[6];
    float* out = (float*)d_out;

    void *pQ, *pK, *pVt;
    cudaGetSymbolAddress(&pQ, g_Qh);
    cudaGetSymbolAddress(&pK, g_Kh);
    cudaGetSymbolAddress(&pVt, g_Vt);

    cudaFuncSetAttribute(gemm_qkv, cudaFuncAttributeMaxDynamicSharedMemorySize, GSMEM);
    cudaFuncSetAttribute(gemm_o, cudaFuncAttributeMaxDynamicSharedMemorySize, GSMEM);
    cudaFuncSetAttribute(attn_mma, cudaFuncAttributeMaxDynamicSharedMemorySize, ASMEM);

    // Pre-pass: bf16 hi/lo split of all inputs (one launch)
    dim3 rgrid(NBIG4 / 256, 7);
    split_all<<<rgrid, 256>>>(
        (const float4*)q, (const float4*)k, (const float4*)v,
        (const float4*)Wq, (const float4*)Wk, (const float4*)Wv, (const float4*)Wo);

    // Fused Q/K/V projections (bf16-split MMA)
    dim3 qkv_grid(DD / 128, MM / 128, 3);   // (8, 64, 3)
    gemm_qkv<<<qkv_grid, 256, GSMEM>>>((float*)pQ, (float*)pK, (float*)pVt);

    // Attention (tf32)
    dim3 attn_grid(SS / QT, HH, BB);        // (16, 16, 4)
    attn_mma<<<attn_grid, 128, ASMEM>>>((const float*)pQ, (const float*)pK,
                                        (const float*)pVt);

    // Output projection (bf16-split MMA)
    dim3 o_grid(DD / 128, MM / 128);        // (8, 64)
    gemm_o<<<o_grid, 256, GSMEM>>>(out);
}

// round 13
// speedup vs baseline: 2.2342x; 2.2342x over previous
#include <cuda_runtime.h>
#include <cuda_fp16.h>
#include <cstdint>
#include <cstddef>

// Problem constants
#define BB 4
#define SS 2048
#define DD 1024
#define HH 16
#define DK 64
#define MM (BB * SS)   // 8192

// fp16 operands
__device__ __half g_q16[(size_t)MM * DD];        // q * 0.125 (softmax scale folded)
__device__ __half g_k16[(size_t)MM * DD];
__device__ __half g_v16[(size_t)MM * DD];
__device__ __half g_Wq16[DD * DD];
__device__ __half g_Wk16[DD * DD];
__device__ __half g_Wv16[DD * DD];
__device__ __half g_Wo16[DD * DD];
__device__ __half g_Q16[(size_t)MM * DD];        // [B,H,S,DK]
__device__ __half g_K16[(size_t)MM * DD];        // [B,H,S,DK]
__device__ __half g_Vt16[(size_t)MM * DD];       // [B,H,DK,S]
__device__ __half g_O16[(size_t)MM * DD];        // [B,H,S,DK]

// ---------------------------------------------------------------------------
// Helpers
// ---------------------------------------------------------------------------
__device__ __forceinline__ uint32_t smem_u32(const void* p) {
    uint32_t a;
    asm("{ .reg .u64 t; cvta.to.shared.u64 t, %1; cvt.u32.u64 %0, t; }"
        : "=r"(a) : "l"(p));
    return a;
}
__device__ __forceinline__ void cp16(uint32_t saddr, const void* gptr) {
    asm volatile("cp.async.ca.shared.global [%0], [%1], 16;"
                 :: "r"(saddr), "l"(gptr) : "memory");
}
__device__ __forceinline__ void cp_commit() {
    asm volatile("cp.async.commit_group;" ::: "memory");
}
template <int N>
__device__ __forceinline__ void cp_wait() {
    asm volatile("cp.async.wait_group %0;" :: "n"(N) : "memory");
}
// pack two fp32 -> f16x2 register (lo = first k element)
__device__ __forceinline__ uint32_t pack_h2(float lo, float hi) {
    uint32_t u;
    asm("cvt.rn.f16x2.f32 %0, %1, %2;" : "=r"(u) : "f"(hi), "f"(lo));
    return u;
}
__device__ __forceinline__ void mma_f16(float* d, const uint32_t* a, const uint32_t* b) {
    asm volatile(
        "mma.sync.aligned.m16n8k16.row.col.f32.f16.f16.f32 "
        "{%0,%1,%2,%3}, {%4,%5,%6,%7}, {%8,%9}, {%0,%1,%2,%3};"
        : "+f"(d[0]), "+f"(d[1]), "+f"(d[2]), "+f"(d[3])
        : "r"(a[0]), "r"(a[1]), "r"(a[2]), "r"(a[3]), "r"(b[0]), "r"(b[1]));
}
__device__ __forceinline__ void ldsm4(uint32_t* r, uint32_t addr) {
    asm volatile("ldmatrix.sync.aligned.m8n8.x4.shared.b16 {%0,%1,%2,%3}, [%4];"
                 : "=r"(r[0]), "=r"(r[1]), "=r"(r[2]), "=r"(r[3]) : "r"(addr));
}

// ---------------------------------------------------------------------------
// Pre-pass: fp16 conversion of all 7 inputs. grid (8192, 7). q scaled 0.125.
// ---------------------------------------------------------------------------
#define NBIG4 ((int)((size_t)MM * DD / 4))   // 2097152
#define NW4 (DD * DD / 4)                    // 262144

__global__ __launch_bounds__(256)
void cvt_all(const float4* __restrict__ q, const float4* __restrict__ k,
             const float4* __restrict__ v, const float4* __restrict__ Wq,
             const float4* __restrict__ Wk, const float4* __restrict__ Wv,
             const float4* __restrict__ Wo)
{
    const int y = blockIdx.y;
    const int i = blockIdx.x * blockDim.x + threadIdx.x;
    const float4* src;
    __half* dst;
    int n4;
    float scale = 1.0f;
    switch (y) {
        case 0: src = q;  dst = g_q16;  n4 = NBIG4; scale = 0.125f; break;
        case 1: src = k;  dst = g_k16;  n4 = NBIG4; break;
        case 2: src = v;  dst = g_v16;  n4 = NBIG4; break;
        case 3: src = Wq; dst = g_Wq16; n4 = NW4; break;
        case 4: src = Wk; dst = g_Wk16; n4 = NW4; break;
        case 5: src = Wv; dst = g_Wv16; n4 = NW4; break;
        default: src = Wo; dst = g_Wo16; n4 = NW4; break;
    }
    if (i < n4) {
        float4 x = src[i];
        x.x *= scale; x.y *= scale; x.z *= scale; x.w *= scale;
        __half2 h0 = __floats2half2_rn(x.x, x.y);
        __half2 h1 = __floats2half2_rn(x.z, x.w);
        *(__half2*)&dst[(size_t)i * 4]     = h0;
        *(__half2*)&dst[(size_t)i * 4 + 2] = h1;
    }
}

// ---------------------------------------------------------------------------
// fp16 GEMM core: C = A @ W^T, tile 128x128, BK=64, 256 threads, 8 warps 64x32.
// 2-stage cp.async pipeline.
// ---------------------------------------------------------------------------
#define RH 72                          // halves per smem row (64 + pad 8)
#define TILEB (128 * RH * 2)           // 18432 bytes per tile
#define BUFB (2 * TILEB)               // A + B = 36864
#define GSMEM (2 * BUFB)               // 73728
#define NCHUNK (DD / 64)               // 16

template <bool GATHER>
__device__ __forceinline__ void issue_chunk(uint32_t sbuf, int it,
                                            const __half* __restrict__ A,
                                            const __half* __restrict__ W,
                                            int bm, int bn, int tid)
{
    const int k0 = it * 64;
    #pragma unroll
    for (int i = 0; i < 4; i++) {
        const int idx = i * 256 + tid;       // 0..1023 (8-half slots)
        const int r = idx >> 3;              // 0..127
        const int c8 = idx & 7;
        const int gk = k0 + c8 * 8;
        size_t aoff;
        if (GATHER) {
            const int gm = bm + r;
            const int b = gm >> 11;
            const int s = gm & (SS - 1);
            const int h = gk >> 6;
            const int dk = gk & (DK - 1);
            aoff = ((((size_t)b * HH + h) * SS + s) << 6) + dk;
        } else {
            aoff = (size_t)(bm + r) * DD + gk;
        }
        const uint32_t soff = (uint32_t)(r * RH + c8 * 8) * 2u;
        cp16(sbuf + soff, &A[aoff]);
        cp16(sbuf + TILEB + soff, &W[(size_t)(bn + r) * DD + gk]);
    }
    cp_commit();
}

template <bool GATHER>
__device__ __forceinline__ void gemm_core(const __half* __restrict__ A,
                                          const __half* __restrict__ W,
                                          float (&acc)[4][4][4],
                                          int bm, int bn, char* smem)
{
    const uint32_t sb = smem_u32(smem);
    const int tid = threadIdx.x;
    const int lane = tid & 31;
    const int wid = tid >> 5;
    const int wm = wid >> 2;        // 0..1
    const int wn = wid & 3;         // 0..3
    const uint32_t lrow = (uint32_t)(lane & 15);
    const uint32_t lcol = (uint32_t)(lane >> 4) * 8u;

    const uint32_t aoff = ((wm * 64 + lrow) * RH + lcol) * 2u;
    const uint32_t boff = ((wn * 32 + lrow) * RH + lcol) * 2u;

    const uint32_t sbuf[2] = { sb, sb + (uint32_t)BUFB };

    issue_chunk<GATHER>(sbuf[0], 0, A, W, bm, bn, tid);

    for (int it = 0; it < NCHUNK; ++it) {
        const int cur = it & 1;
        if (it + 1 < NCHUNK) {
            issue_chunk<GATHER>(sbuf[cur ^ 1], it + 1, A, W, bm, bn, tid);
            cp_wait<1>();
        } else {
            cp_wait<0>();
        }
        __syncthreads();

        const uint32_t aT = sbuf[cur] + aoff;
        const uint32_t bT = sbuf[cur] + TILEB + boff;
        #pragma unroll
        for (int ks = 0; ks < 4; ks++) {        // 4 k16 steps per 64-chunk
            const uint32_t koff = (uint32_t)ks * 32u;   // 16 halves
            uint32_t afr[4][4], bfr[4][2];
            #pragma unroll
            for (int mt = 0; mt < 4; mt++)
                ldsm4(afr[mt], aT + (uint32_t)(mt * 16 * RH) * 2u + koff);
            #pragma unroll
            for (int p = 0; p < 2; p++) {
                uint32_t r4[4];
                ldsm4(r4, bT + (uint32_t)(p * 16 * RH) * 2u + koff);
                bfr[2 * p][0] = r4[0]; bfr[2 * p][1] = r4[2];
                bfr[2 * p + 1][0] = r4[1]; bfr[2 * p + 1][1] = r4[3];
            }
            #pragma unroll
            for (int mt = 0; mt < 4; mt++)
                #pragma unroll
                for (int nt = 0; nt < 4; nt++)
                    mma_f16(acc[mt][nt], afr[mt], bfr[nt]);
        }
        __syncthreads();
    }
}

// Fused Q/K/V projections: grid (8, 64, 3). z=0 -> Q16, z=1 -> K16, z=2 -> Vt16.
__global__ __launch_bounds__(256, 2)
void gemm_qkv()
{
    extern __shared__ char smem[];
    const int z = blockIdx.z;
    const __half *A, *W;
    __half* C;
    if (z == 0) { A = g_q16; W = g_Wq16; C = g_Q16; }
    else if (z == 1) { A = g_k16; W = g_Wk16; C = g_K16; }
    else { A = g_v16; W = g_Wv16; C = g_Vt16; }
    const int bm = blockIdx.y * 128;
    const int bn = blockIdx.x * 128;

    float acc[4][4][4];
    #pragma unroll
    for (int i = 0; i < 4; i++)
        #pragma unroll
        for (int j = 0; j < 4; j++)
            #pragma unroll
            for (int r = 0; r < 4; r++) acc[i][j][r] = 0.f;

    gemm_core<false>(A, W, acc, bm, bn, smem);

    const int lane = threadIdx.x & 31;
    const int wid = threadIdx.x >> 5;
    const int g = lane >> 2;
    const int tig = lane & 3;
    const int wm = wid >> 2;
    const int wn = wid & 3;

    #pragma unroll
    for (int mt = 0; mt < 4; mt++) {
        #pragma unroll
        for (int half = 0; half < 2; half++) {
            const int gm = bm + wm * 64 + mt * 16 + g + half * 8;
            const int b = gm >> 11;
            const int s = gm & (SS - 1);
            #pragma unroll
            for (int nt = 0; nt < 4; nt++) {
                const int gn = bn + wn * 32 + nt * 8 + 2 * tig;
                const float vx = acc[mt][nt][half * 2 + 0];
                const float vy = acc[mt][nt][half * 2 + 1];
                const int h = gn >> 6;
                const int dk = gn & (DK - 1);
                if (z < 2) {
                    *(__half2*)&C[((((size_t)b * HH + h) * SS + s) << 6) + dk] =
                        __floats2half2_rn(vx, vy);
                } else {
                    const size_t base = (((size_t)b * HH + h) * DK);
                    C[(base + dk) * SS + s] = __float2half_rn(vx);
                    C[(base + dk + 1) * SS + s] = __float2half_rn(vy);
                }
            }
        }
    }
}

// Output projection: gather-A from head-split O16, fp32 epilogue to out.
__global__ __launch_bounds__(256, 2)
void gemm_o(float* __restrict__ C)
{
    extern __shared__ char smem[];
    const int bm = blockIdx.y * 128;
    const int bn = blockIdx.x * 128;

    float acc[4][4][4];
    #pragma unroll
    for (int i = 0; i < 4; i++)
        #pragma unroll
        for (int j = 0; j < 4; j++)
            #pragma unroll
            for (int r = 0; r < 4; r++) acc[i][j][r] = 0.f;

    gemm_core<true>(g_O16, g_Wo16, acc, bm, bn, smem);

    const int lane = threadIdx.x & 31;
    const int wid = threadIdx.x >> 5;
    const int g = lane >> 2;
    const int tig = lane & 3;
    const int wm = wid >> 2;
    const int wn = wid & 3;

    #pragma unroll
    for (int mt = 0; mt < 4; mt++) {
        #pragma unroll
        for (int half = 0; half < 2; half++) {
            const int gm = bm + wm * 64 + mt * 16 + g + half * 8;
            #pragma unroll
            for (int nt = 0; nt < 4; nt++) {
                const int gn = bn + wn * 32 + nt * 8 + 2 * tig;
                float2 o;
                o.x = acc[mt][nt][half * 2 + 0];
                o.y = acc[mt][nt][half * 2 + 1];
                *(float2*)&C[(size_t)gm * DD + gn] = o;
            }
        }
    }
}

// ---------------------------------------------------------------------------
// fp16 causal flash attention. Q16 (pre-scaled)/K16 [B,H,S,DK]; Vt16 [B,H,DK,S].
// CTA = 128 queries, 128 threads (each warp: 32 queries = 2 m16 groups).
// m16n8k16 MMA; S C-fragment == P A-fragment layout -> NO shfl transpose.
// ---------------------------------------------------------------------------
#define QT 128
#define AST 72
#define ATILEB (64 * AST * 2)          // 9216 bytes per K/V tile
#define ASMEM (4 * ATILEB)             // 36864 bytes

__device__ __forceinline__ void attn_stage(uint32_t sK, uint32_t sV,
                                           const __half* __restrict__ Kh,
                                           const __half* __restrict__ Vt,
                                           size_t headoff, int kb, int tid)
{
    #pragma unroll
    for (int i = 0; i < 4; i++) {
        const int idx = i * 128 + tid;       // 0..511 (8-half slots)
        const int r = idx >> 3;              // 0..63
        const int c8 = idx & 7;
        const uint32_t soff = (uint32_t)(r * AST + c8 * 8) * 2u;
        cp16(sK + soff, &Kh[headoff + (size_t)(kb * 64 + r) * DK + c8 * 8]);
        cp16(sV + soff, &Vt[headoff + (size_t)r * SS + kb * 64 + c8 * 8]);
    }
    cp_commit();
}

__global__ __launch_bounds__(128, 2)
void attn_mma(const __half* __restrict__ Qh, const __half* __restrict__ Kh,
              const __half* __restrict__ Vt)
{
    extern __shared__ char smc[];
    const uint32_t sb = smem_u32(smc);
    const uint32_t sK[2] = { sb, sb + (uint32_t)ATILEB };
    const uint32_t sV[2] = { sb + 2u * ATILEB, sb + 3u * ATILEB };

    const int tid = threadIdx.x;
    const int wid = tid >> 5;
    const int lane = tid & 31;
    const int g = lane >> 2;
    const int tig = lane & 3;
    const uint32_t lrow = (uint32_t)(lane & 15);
    const uint32_t lcol = (uint32_t)(lane >> 4) * 8u;
    const int qt = gridDim.x - 1 - blockIdx.x;   // heavy tiles first
    const int h = blockIdx.y;
    const int b = blockIdx.z;
    const size_t headoff = ((size_t)(b * HH + h)) * SS * DK;
    const int nkb = 2 * qt + 2;

    // Stage 128 Q rows into the contiguous sK[0]|sK[1] region (stride AST).
    #pragma unroll
    for (int i = 0; i < 8; i++) {
        const int idx = i * 128 + tid;       // 0..1023
        const int r = idx >> 3;
        const int c8 = idx & 7;
        cp16(sK[0] + (uint32_t)(r * AST + c8 * 8) * 2u,
             &Qh[headoff + (size_t)(qt * QT + r) * DK + c8 * 8]);
    }
    cp_commit();
    cp_wait<0>();
    __syncthreads();

    // Q fragments: 2 groups x 4 k16 steps x 4 regs.
    uint32_t qf[2][4][4];
    #pragma unroll
    for (int grp = 0; grp < 2; grp++) {
        const uint32_t qbase = sK[0]
            + ((wid * 32 + grp * 16 + lrow) * AST + lcol) * 2u;
        #pragma unroll
        for (int ks = 0; ks < 4; ks++)
            ldsm4(qf[grp][ks], qbase + (uint32_t)ks * 32u);
    }
    __syncthreads();

    attn_stage(sK[0], sV[0], Kh, Vt, headoff, 0, tid);

    const uint32_t foff = (lrow * AST + lcol) * 2u;

    float oacc[2][8][4];
    #pragma unroll
    for (int grp = 0; grp < 2; grp++)
        #pragma unroll
        for (int nt = 0; nt < 8; nt++)
            #pragma unroll
            for (int r = 0; r < 4; r++) oacc[grp][nt][r] = 0.f;
    float m[2][2] = { {-1e30f, -1e30f}, {-1e30f, -1e30f} };
    float l[2][2] = { {0.f, 0.f}, {0.f, 0.f} };

    for (int kb = 0; kb < nkb; kb++) {
        const int cur = kb & 1;
        if (kb + 1 < nkb) {
            attn_stage(sK[cur ^ 1], sV[cur ^ 1], Kh, Vt, headoff, kb + 1, tid);
            cp_wait<1>();
        } else {
            cp_wait<0>();
        }
        __syncthreads();

        // ---- S = Q K^T (k16 MMA, shared K fragments across groups) ----
        float sacc[2][8][4];
        #pragma unroll
        for (int grp = 0; grp < 2; grp++)
            #pragma unroll
            for (int nt = 0; nt < 8; nt++)
                #pragma unroll
                for (int r = 0; r < 4; r++) sacc[grp][nt][r] = 0.f;

        const uint32_t kT = sK[cur] + foff;
        #pragma unroll
        for (int ks = 0; ks < 4; ks++) {
            uint32_t bfr[8][2];
            #pragma unroll
            for (int p = 0; p < 4; p++) {
                uint32_t r4[4];
                ldsm4(r4, kT + (uint32_t)(p * 16 * AST) * 2u + (uint32_t)ks * 32u);
                bfr[2 * p][0] = r4[0]; bfr[2 * p][1] = r4[2];
                bfr[2 * p + 1][0] = r4[1]; bfr[2 * p + 1][1] = r4[3];
            }
            #pragma unroll
            for (int grp = 0; grp < 2; grp++)
                #pragma unroll
                for (int nt = 0; nt < 8; nt++)
                    mma_f16(sacc[grp][nt], qf[grp][ks], bfr[nt]);
        }

        // ---- causal mask (last two k-blocks only) ----
        const int rel = (kb - 2 * qt) * 64;
        if (rel >= 0) {
            #pragma unroll
            for (int grp = 0; grp < 2; grp++) {
                const int ql0 = wid * 32 + grp * 16 + g;
                const int ql1 = ql0 + 8;
                #pragma unroll
                for (int nt = 0; nt < 8; nt++) {
                    const int kc = rel + nt * 8 + 2 * tig;
                    if (kc > ql0)     sacc[grp][nt][0] = -1e30f;
                    if (kc + 1 > ql0) sacc[grp][nt][1] = -1e30f;
                    if (kc > ql1)     sacc[grp][nt][2] = -1e30f;
                    if (kc + 1 > ql1) sacc[grp][nt][3] = -1e30f;
                }
            }
        }

        // ---- online softmax bookkeeping per group ----
        float nm[2][2];
        #pragma unroll
        for (int grp = 0; grp < 2; grp++) {
            float tmax0 = -1e30f, tmax1 = -1e30f;
            #pragma unroll
            for (int nt = 0; nt < 8; nt++) {
                tmax0 = fmaxf(tmax0, fmaxf(sacc[grp][nt][0], sacc[grp][nt][1]));
                tmax1 = fmaxf(tmax1, fmaxf(sacc[grp][nt][2], sacc[grp][nt][3]));
            }
            tmax0 = fmaxf(tmax0, __shfl_xor_sync(0xffffffffu, tmax0, 1));
            tmax0 = fmaxf(tmax0, __shfl_xor_sync(0xffffffffu, tmax0, 2));
            tmax1 = fmaxf(tmax1, __shfl_xor_sync(0xffffffffu, tmax1, 1));
            tmax1 = fmaxf(tmax1, __shfl_xor_sync(0xffffffffu, tmax1, 2));
            const float nm0 = fmaxf(m[grp][0], tmax0);
            const float nm1 = fmaxf(m[grp][1], tmax1);
            const float corr0 = __expf(m[grp][0] - nm0);
            const float corr1 = __expf(m[grp][1] - nm1);
            l[grp][0] *= corr0;
            l[grp][1] *= corr1;
            #pragma unroll
            for (int nt = 0; nt < 8; nt++) {
                oacc[grp][nt][0] *= corr0; oacc[grp][nt][1] *= corr0;
                oacc[grp][nt][2] *= corr1; oacc[grp][nt][3] *= corr1;
            }
            m[grp][0] = nm0; m[grp][1] = nm1;
            nm[grp][0] = nm0; nm[grp][1] = nm1;
        }

        // ---- PV: exp in C layout == A layout, pack f16x2, mma. No shfl. ----
        const uint32_t vT = sV[cur] + foff;
        #pragma unroll
        for (int ks2 = 0; ks2 < 4; ks2++) {     // 16 keys per step
            uint32_t bfr[8][2];
            #pragma unroll
            for (int p = 0; p < 4; p++) {
                uint32_t r4[4];
                ldsm4(r4, vT + (uint32_t)(p * 16 * AST) * 2u + (uint32_t)ks2 * 32u);
                bfr[2 * p][0] = r4[0]; bfr[2 * p][1] = r4[2];
                bfr[2 * p + 1][0] = r4[1]; bfr[2 * p + 1][1] = r4[3];
            }
            #pragma unroll
            for (int grp = 0; grp < 2; grp++) {
                const int nt0 = 2 * ks2, nt1 = 2 * ks2 + 1;
                const float p00 = __expf(sacc[grp][nt0][0] - nm[grp][0]);
                const float p01 = __expf(sacc[grp][nt0][1] - nm[grp][0]);
                const float p02 = __expf(sacc[grp][nt0][2] - nm[grp][1]);
                const float p03 = __expf(sacc[grp][nt0][3] - nm[grp][1]);
                const float p10 = __expf(sacc[grp][nt1][0] - nm[grp][0]);
                const float p11 = __expf(sacc[grp][nt1][1] - nm[grp][0]);
                const float p12 = __expf(sacc[grp][nt1][2] - nm[grp][1]);
                const float p13 = __expf(sacc[grp][nt1][3] - nm[grp][1]);
                l[grp][0] += (p00 + p01) + (p10 + p11);
                l[grp][1] += (p02 + p03) + (p12 + p13);
                uint32_t af[4];
                af[0] = pack_h2(p00, p01);   // row g,   keys 2tig..
                af[1] = pack_h2(p02, p03);   // row g+8
                af[2] = pack_h2(p10, p11);   // row g,   keys 2tig+8..
                af[3] = pack_h2(p12, p13);   // row g+8
                #pragma unroll
                for (int nt = 0; nt < 8; nt++)
                    mma_f16(oacc[grp][nt], af, bfr[nt]);
            }
        }
        __syncthreads();
    }

    // Epilogue: O as fp16 head-split (consumed by gemm_o).
    #pragma unroll
    for (int grp = 0; grp < 2; grp++) {
        float la = l[grp][0], lb = l[grp][1];
        la += __shfl_xor_sync(0xffffffffu, la, 1);
        la += __shfl_xor_sync(0xffffffffu, la, 2);
        lb += __shfl_xor_sync(0xffffffffu, lb, 1);
        lb += __shfl_xor_sync(0xffffffffu, lb, 2);
        const float inv0 = 1.f / la;
        const float inv1 = 1.f / lb;
        const int qr0 = qt * QT + wid * 32 + grp * 16 + g;
        const int qr1 = qr0 + 8;
        #pragma unroll
        for (int nt = 0; nt < 8; nt++) {
            const int d = nt * 8 + 2 * tig;
            const size_t off0 = headoff + (size_t)qr0 * DK + d;
            const size_t off1 = headoff + (size_t)qr1 * DK + d;
            *(__half2*)&g_O16[off0] =
                __floats2half2_rn(oacc[grp][nt][0] * inv0, oacc[grp][nt][1] * inv0);
            *(__half2*)&g_O16[off1] =
                __floats2half2_rn(oacc[grp][nt][2] * inv1, oacc[grp][nt][3] * inv1);
        }
    }
}

// ---------------------------------------------------------------------------
extern "C" void kernel_launch(void* const* d_in, const int* in_sizes, int n_in,
                              void* d_out, int out_size)
{
    const float* q  = (const float*)d_in[0];
    const float* k  = (const float*)d_in[1];
    const float* v  = (const float*)d_in[2];
    const float* Wq = (const float*)d_in[3];
    const float* Wk = (const float*)d_in[4];
    const float* Wv = (const float*)d_in[5];
    const float* Wo = (const float*)d_in[6];
    float* out = (float*)d_out;

    void *pQ, *pK, *pVt;
    cudaGetSymbolAddress(&pQ, g_Q16);
    cudaGetSymbolAddress(&pK, g_K16);
    cudaGetSymbolAddress(&pVt, g_Vt16);

    cudaFuncSetAttribute(gemm_qkv, cudaFuncAttributeMaxDynamicSharedMemorySize, GSMEM);
    cudaFuncSetAttribute(gemm_o, cudaFuncAttributeMaxDynamicSharedMemorySize, GSMEM);
    cudaFuncSetAttribute(attn_mma, cudaFuncAttributeMaxDynamicSharedMemorySize, ASMEM);

    // Pre-pass
    dim3 rgrid(NBIG4 / 256, 7);
    cvt_all<<<rgrid, 256>>>(
        (const float4*)q, (const float4*)k, (const float4*)v,
        (const float4*)Wq, (const float4*)Wk, (const float4*)Wv, (const float4*)Wo);

    // Fused Q/K/V projections
    dim3 qkv_grid(DD / 128, MM / 128, 3);   // (8, 64, 3)
    gemm_qkv<<<qkv_grid, 256, GSMEM>>>();

    // Attention
    dim3 attn_grid(SS / QT, HH, BB);        // (16, 16, 4)
    attn_mma<<<attn_grid, 128, ASMEM>>>((const __half*)pQ, (const __half*)pK,
                                        (const __half*)pVt);

    // Output projection
    dim3 o_grid(DD / 128, MM / 128);        // (8, 64)
    gemm_o<<<o_grid, 256, GSMEM>>>(out);
}

// round 14
// speedup vs baseline: 2.2591x; 1.0112x over previous
#include <cuda_runtime.h>
#include <cuda_fp16.h>
#include <cstdint>
#include <cstddef>

// Problem constants
#define BB 4
#define SS 2048
#define DD 1024
#define HH 16
#define DK 64
#define MM (BB * SS)   // 8192

// fp16 operands
__device__ __half g_q16[(size_t)MM * DD];        // q * 0.125 (softmax scale folded)
__device__ __half g_k16[(size_t)MM * DD];
__device__ __half g_v16[(size_t)MM * DD];
__device__ __half g_Wq16[DD * DD];
__device__ __half g_Wk16[DD * DD];
__device__ __half g_Wv16[DD * DD];
__device__ __half g_Wo16[DD * DD];
__device__ __half g_Q16[(size_t)MM * DD];        // [B,H,S,DK]
__device__ __half g_K16[(size_t)MM * DD];        // [B,H,S,DK]
__device__ __half g_Vt16[(size_t)MM * DD];       // [B,H,DK,S]
__device__ __half g_O16[(size_t)MM * DD];        // [B,H,S,DK]

// ---------------------------------------------------------------------------
// Helpers
// ---------------------------------------------------------------------------
__device__ __forceinline__ uint32_t smem_u32(const void* p) {
    uint32_t a;
    asm("{ .reg .u64 t; cvta.to.shared.u64 t, %1; cvt.u32.u64 %0, t; }"
        : "=r"(a) : "l"(p));
    return a;
}
__device__ __forceinline__ void cp16(uint32_t saddr, const void* gptr) {
    asm volatile("cp.async.ca.shared.global [%0], [%1], 16;"
                 :: "r"(saddr), "l"(gptr) : "memory");
}
__device__ __forceinline__ void cp_commit() {
    asm volatile("cp.async.commit_group;" ::: "memory");
}
template <int N>
__device__ __forceinline__ void cp_wait() {
    asm volatile("cp.async.wait_group %0;" :: "n"(N) : "memory");
}
// pack two fp32 -> f16x2 register (lo = first k element)
__device__ __forceinline__ uint32_t pack_h2(float lo, float hi) {
    uint32_t u;
    asm("cvt.rn.f16x2.f32 %0, %1, %2;" : "=r"(u) : "f"(hi), "f"(lo));
    return u;
}
__device__ __forceinline__ void mma_f16(float* d, const uint32_t* a, const uint32_t* b) {
    asm volatile(
        "mma.sync.aligned.m16n8k16.row.col.f32.f16.f16.f32 "
        "{%0,%1,%2,%3}, {%4,%5,%6,%7}, {%8,%9}, {%0,%1,%2,%3};"
        : "+f"(d[0]), "+f"(d[1]), "+f"(d[2]), "+f"(d[3])
        : "r"(a[0]), "r"(a[1]), "r"(a[2]), "r"(a[3]), "r"(b[0]), "r"(b[1]));
}
__device__ __forceinline__ void ldsm4(uint32_t* r, uint32_t addr) {
    asm volatile("ldmatrix.sync.aligned.m8n8.x4.shared.b16 {%0,%1,%2,%3}, [%4];"
                 : "=r"(r[0]), "=r"(r[1]), "=r"(r[2]), "=r"(r[3]) : "r"(addr));
}

// ---------------------------------------------------------------------------
// Pre-pass: fp16 conversion of all 7 inputs. grid (8192, 7). q scaled 0.125.
// ---------------------------------------------------------------------------
#define NBIG4 ((int)((size_t)MM * DD / 4))   // 2097152
#define NW4 (DD * DD / 4)                    // 262144

__global__ __launch_bounds__(256)
void cvt_all(const float4* __restrict__ q, const float4* __restrict__ k,
             const float4* __restrict__ v, const float4* __restrict__ Wq,
             const float4* __restrict__ Wk, const float4* __restrict__ Wv,
             const float4* __restrict__ Wo)
{
    const int y = blockIdx.y;
    const int i = blockIdx.x * blockDim.x + threadIdx.x;
    const float4* src;
    __half* dst;
    int n4;
    float scale = 1.0f;
    switch (y) {
        case 0: src = q;  dst = g_q16;  n4 = NBIG4; scale = 0.125f; break;
        case 1: src = k;  dst = g_k16;  n4 = NBIG4; break;
        case 2: src = v;  dst = g_v16;  n4 = NBIG4; break;
        case 3: src = Wq; dst = g_Wq16; n4 = NW4; break;
        case 4: src = Wk; dst = g_Wk16; n4 = NW4; break;
        case 5: src = Wv; dst = g_Wv16; n4 = NW4; break;
        default: src = Wo; dst = g_Wo16; n4 = NW4; break;
    }
    if (i < n4) {
        float4 x = src[i];
        x.x *= scale; x.y *= scale; x.z *= scale; x.w *= scale;
        __half2 h0 = __floats2half2_rn(x.x, x.y);
        __half2 h1 = __floats2half2_rn(x.z, x.w);
        *(__half2*)&dst[(size_t)i * 4]     = h0;
        *(__half2*)&dst[(size_t)i * 4 + 2] = h1;
    }
}

// ---------------------------------------------------------------------------
// fp16 GEMM core: C = A @ W^T, tile 128x128, BK=64, 128 threads, 4 warps 64x64.
// 2-stage cp.async pipeline.
// ---------------------------------------------------------------------------
#define RH 72                          // halves per smem row (64 + pad 8)
#define TILEB (128 * RH * 2)           // 18432 bytes per tile
#define BUFB (2 * TILEB)               // A + B = 36864
#define GSMEM (2 * BUFB)               // 73728
#define NCHUNK (DD / 64)               // 16

template <bool GATHER>
__device__ __forceinline__ void issue_chunk(uint32_t sbuf, int it,
                                            const __half* __restrict__ A,
                                            const __half* __restrict__ W,
                                            int bm, int bn, int tid)
{
    const int k0 = it * 64;
    #pragma unroll
    for (int i = 0; i < 8; i++) {
        const int idx = i * 128 + tid;       // 0..1023 (8-half slots)
        const int r = idx >> 3;              // 0..127
        const int c8 = idx & 7;
        const int gk = k0 + c8 * 8;
        size_t aoff;
        if (GATHER) {
            const int gm = bm + r;
            const int b = gm >> 11;
            const int s = gm & (SS - 1);
            const int h = gk >> 6;
            const int dk = gk & (DK - 1);
            aoff = ((((size_t)b * HH + h) * SS + s) << 6) + dk;
        } else {
            aoff = (size_t)(bm + r) * DD + gk;
        }
        const uint32_t soff = (uint32_t)(r * RH + c8 * 8) * 2u;
        cp16(sbuf + soff, &A[aoff]);
        cp16(sbuf + TILEB + soff, &W[(size_t)(bn + r) * DD + gk]);
    }
    cp_commit();
}

template <bool GATHER>
__device__ __forceinline__ void gemm_core(const __half* __restrict__ A,
                                          const __half* __restrict__ W,
                                          float (&acc)[4][8][4],
                                          int bm, int bn, char* smem)
{
    const uint32_t sb = smem_u32(smem);
    const int tid = threadIdx.x;
    const int lane = tid & 31;
    const int wid = tid >> 5;       // 0..3
    const int wm = wid >> 1;        // 0..1 (64-row slab)
    const int wn = wid & 1;         // 0..1 (64-col slab)
    const uint32_t lrow = (uint32_t)(lane & 15);
    const uint32_t lcol = (uint32_t)(lane >> 4) * 8u;

    const uint32_t aoff = ((wm * 64 + lrow) * RH + lcol) * 2u;
    const uint32_t boff = ((wn * 64 + lrow) * RH + lcol) * 2u;

    const uint32_t sbuf[2] = { sb, sb + (uint32_t)BUFB };

    issue_chunk<GATHER>(sbuf[0], 0, A, W, bm, bn, tid);

    for (int it = 0; it < NCHUNK; ++it) {
        const int cur = it & 1;
        if (it + 1 < NCHUNK) {
            issue_chunk<GATHER>(sbuf[cur ^ 1], it + 1, A, W, bm, bn, tid);
            cp_wait<1>();
        } else {
            cp_wait<0>();
        }
        __syncthreads();

        const uint32_t aT = sbuf[cur] + aoff;
        const uint32_t bT = sbuf[cur] + TILEB + boff;
        #pragma unroll
        for (int ks = 0; ks < 4; ks++) {        // 4 k16 steps per 64-chunk
            const uint32_t koff = (uint32_t)ks * 32u;   // 16 halves
            uint32_t afr[4][4], bfr[8][2];
            #pragma unroll
            for (int mt = 0; mt < 4; mt++)
                ldsm4(afr[mt], aT + (uint32_t)(mt * 16 * RH) * 2u + koff);
            #pragma unroll
            for (int p = 0; p < 4; p++) {
                uint32_t r4[4];
                ldsm4(r4, bT + (uint32_t)(p * 16 * RH) * 2u + koff);
                bfr[2 * p][0] = r4[0]; bfr[2 * p][1] = r4[2];
                bfr[2 * p + 1][0] = r4[1]; bfr[2 * p + 1][1] = r4[3];
            }
            #pragma unroll
            for (int mt = 0; mt < 4; mt++)
                #pragma unroll
                for (int nt = 0; nt < 8; nt++)
                    mma_f16(acc[mt][nt], afr[mt], bfr[nt]);
        }
        __syncthreads();
    }
}

// Fused Q/K/V projections: grid (8, 64, 3). z=0 -> Q16, z=1 -> K16, z=2 -> Vt16.
__global__ __launch_bounds__(128, 2)
void gemm_qkv()
{
    extern __shared__ char smem[];
    const int z = blockIdx.z;
    const __half *A, *W;
    __half* C;
    if (z == 0) { A = g_q16; W = g_Wq16; C = g_Q16; }
    else if (z == 1) { A = g_k16; W = g_Wk16; C = g_K16; }
    else { A = g_v16; W = g_Wv16; C = g_Vt16; }
    const int bm = blockIdx.y * 128;
    const int bn = blockIdx.x * 128;

    float acc[4][8][4];
    #pragma unroll
    for (int i = 0; i < 4; i++)
        #pragma unroll
        for (int j = 0; j < 8; j++)
            #pragma unroll
            for (int r = 0; r < 4; r++) acc[i][j][r] = 0.f;

    gemm_core<false>(A, W, acc, bm, bn, smem);

    const int lane = threadIdx.x & 31;
    const int wid = threadIdx.x >> 5;
    const int g = lane >> 2;
    const int tig = lane & 3;
    const int wm = wid >> 1;
    const int wn = wid & 1;

    #pragma unroll
    for (int mt = 0; mt < 4; mt++) {
        #pragma unroll
        for (int half = 0; half < 2; half++) {
            const int gm = bm + wm * 64 + mt * 16 + g + half * 8;
            const int b = gm >> 11;
            const int s = gm & (SS - 1);
            #pragma unroll
            for (int nt = 0; nt < 8; nt++) {
                const int gn = bn + wn * 64 + nt * 8 + 2 * tig;
                const float vx = acc[mt][nt][half * 2 + 0];
                const float vy = acc[mt][nt][half * 2 + 1];
                const int h = gn >> 6;
                const int dk = gn & (DK - 1);
                if (z < 2) {
                    *(__half2*)&C[((((size_t)b * HH + h) * SS + s) << 6) + dk] =
                        __floats2half2_rn(vx, vy);
                } else {
                    const size_t base = (((size_t)b * HH + h) * DK);
                    C[(base + dk) * SS + s] = __float2half_rn(vx);
                    C[(base + dk + 1) * SS + s] = __float2half_rn(vy);
                }
            }
        }
    }
}

// Output projection: gather-A from head-split O16, fp32 epilogue to out.
__global__ __launch_bounds__(128, 2)
void gemm_o(float* __restrict__ C)
{
    extern __shared__ char smem[];
    const int bm = blockIdx.y * 128;
    const int bn = blockIdx.x * 128;

    float acc[4][8][4];
    #pragma unroll
    for (int i = 0; i < 4; i++)
        #pragma unroll
        for (int j = 0; j < 8; j++)
            #pragma unroll
            for (int r = 0; r < 4; r++) acc[i][j][r] = 0.f;

    gemm_core<true>(g_O16, g_Wo16, acc, bm, bn, smem);

    const int lane = threadIdx.x & 31;
    const int wid = threadIdx.x >> 5;
    const int g = lane >> 2;
    const int tig = lane & 3;
    const int wm = wid >> 1;
    const int wn = wid & 1;

    #pragma unroll
    for (int mt = 0; mt < 4; mt++) {
        #pragma unroll
        for (int half = 0; half < 2; half++) {
            const int gm = bm + wm * 64 + mt * 16 + g + half * 8;
            #pragma unroll
            for (int nt = 0; nt < 8; nt++) {
                const int gn = bn + wn * 64 + nt * 8 + 2 * tig;
                float2 o;
                o.x = acc[mt][nt][half * 2 + 0];
                o.y = acc[mt][nt][half * 2 + 1];
                *(float2*)&C[(size_t)gm * DD + gn] = o;
            }
        }
    }
}

// ---------------------------------------------------------------------------
// fp16 causal flash attention (R13 exact). Q16/K16 [B,H,S,DK]; Vt16 [B,H,DK,S].
// CTA = 128 queries, 128 threads (each warp: 32 queries = 2 m16 groups).
// m16n8k16 MMA; S C-fragment == P A-fragment layout -> NO shfl transpose.
// ---------------------------------------------------------------------------
#define QT 128
#define AST 72
#define ATILEB (64 * AST * 2)          // 9216 bytes per K/V tile
#define ASMEM (4 * ATILEB)             // 36864 bytes

__device__ __forceinline__ void attn_stage(uint32_t sK, uint32_t sV,
                                           const __half* __restrict__ Kh,
                                           const __half* __restrict__ Vt,
                                           size_t headoff, int kb, int tid)
{
    #pragma unroll
    for (int i = 0; i < 4; i++) {
        const int idx = i * 128 + tid;       // 0..511 (8-half slots)
        const int r = idx >> 3;              // 0..63
        const int c8 = idx & 7;
        const uint32_t soff = (uint32_t)(r * AST + c8 * 8) * 2u;
        cp16(sK + soff, &Kh[headoff + (size_t)(kb * 64 + r) * DK + c8 * 8]);
        cp16(sV + soff, &Vt[headoff + (size_t)r * SS + kb * 64 + c8 * 8]);
    }
    cp_commit();
}

__global__ __launch_bounds__(128, 2)
void attn_mma(const __half* __restrict__ Qh, const __half* __restrict__ Kh,
              const __half* __restrict__ Vt)
{
    extern __shared__ char smc[];
    const uint32_t sb = smem_u32(smc);
    const uint32_t sK[2] = { sb, sb + (uint32_t)ATILEB };
    const uint32_t sV[2] = { sb + 2u * ATILEB, sb + 3u * ATILEB };

    const int tid = threadIdx.x;
    const int wid = tid >> 5;
    const int lane = tid & 31;
    const int g = lane >> 2;
    const int tig = lane & 3;
    const uint32_t lrow = (uint32_t)(lane & 15);
    const uint32_t lcol = (uint32_t)(lane >> 4) * 8u;
    const int qt = gridDim.x - 1 - blockIdx.x;   // heavy tiles first
    const int h = blockIdx.y;
    const int b = blockIdx.z;
    const size_t headoff = ((size_t)(b * HH + h)) * SS * DK;
    const int nkb = 2 * qt + 2;

    // Stage 128 Q rows into the contiguous sK[0]|sK[1] region (stride AST).
    #pragma unroll
    for (int i = 0; i < 8; i++) {
        const int idx = i * 128 + tid;       // 0..1023
        const int r = idx >> 3;
        const int c8 = idx & 7;
        cp16(sK[0] + (uint32_t)(r * AST + c8 * 8) * 2u,
             &Qh[headoff + (size_t)(qt * QT + r) * DK + c8 * 8]);
    }
    cp_commit();
    cp_wait<0>();
    __syncthreads();

    // Q fragments: 2 groups x 4 k16 steps x 4 regs.
    uint32_t qf[2][4][4];
    #pragma unroll
    for (int grp = 0; grp < 2; grp++) {
        const uint32_t qbase = sK[0]
            + ((wid * 32 + grp * 16 + lrow) * AST + lcol) * 2u;
        #pragma unroll
        for (int ks = 0; ks < 4; ks++)
            ldsm4(qf[grp][ks], qbase + (uint32_t)ks * 32u);
    }
    __syncthreads();

    attn_stage(sK[0], sV[0], Kh, Vt, headoff, 0, tid);

    const uint32_t foff = (lrow * AST + lcol) * 2u;

    float oacc[2][8][4];
    #pragma unroll
    for (int grp = 0; grp < 2; grp++)
        #pragma unroll
        for (int nt = 0; nt < 8; nt++)
            #pragma unroll
            for (int r = 0; r < 4; r++) oacc[grp][nt][r] = 0.f;
    float m[2][2] = { {-1e30f, -1e30f}, {-1e30f, -1e30f} };
    float l[2][2] = { {0.f, 0.f}, {0.f, 0.f} };

    for (int kb = 0; kb < nkb; kb++) {
        const int cur = kb & 1;
        if (kb + 1 < nkb) {
            attn_stage(sK[cur ^ 1], sV[cur ^ 1], Kh, Vt, headoff, kb + 1, tid);
            cp_wait<1>();
        } else {
            cp_wait<0>();
        }
        __syncthreads();

        // ---- S = Q K^T (k16 MMA, shared K fragments across groups) ----
        float sacc[2][8][4];
        #pragma unroll
        for (int grp = 0; grp < 2; grp++)
            #pragma unroll
            for (int nt = 0; nt < 8; nt++)
                #pragma unroll
                for (int r = 0; r < 4; r++) sacc[grp][nt][r] = 0.f;

        const uint32_t kT = sK[cur] + foff;
        #pragma unroll
        for (int ks = 0; ks < 4; ks++) {
            uint32_t bfr[8][2];
            #pragma unroll
            for (int p = 0; p < 4; p++) {
                uint32_t r4[4];
                ldsm4(r4, kT + (uint32_t)(p * 16 * AST) * 2u + (uint32_t)ks * 32u);
                bfr[2 * p][0] = r4[0]; bfr[2 * p][1] = r4[2];
                bfr[2 * p + 1][0] = r4[1]; bfr[2 * p + 1][1] = r4[3];
            }
            #pragma unroll
            for (int grp = 0; grp < 2; grp++)
                #pragma unroll
                for (int nt = 0; nt < 8; nt++)
                    mma_f16(sacc[grp][nt], qf[grp][ks], bfr[nt]);
        }

        // ---- causal mask (last two k-blocks only) ----
        const int rel = (kb - 2 * qt) * 64;
        if (rel >= 0) {
            #pragma unroll
            for (int grp = 0; grp < 2; grp++) {
                const int ql0 = wid * 32 + grp * 16 + g;
                const int ql1 = ql0 + 8;
                #pragma unroll
                for (int nt = 0; nt < 8; nt++) {
                    const int kc = rel + nt * 8 + 2 * tig;
                    if (kc > ql0)     sacc[grp][nt][0] = -1e30f;
                    if (kc + 1 > ql0) sacc[grp][nt][1] = -1e30f;
                    if (kc > ql1)     sacc[grp][nt][2] = -1e30f;
                    if (kc + 1 > ql1) sacc[grp][nt][3] = -1e30f;
                }
            }
        }

        // ---- online softmax bookkeeping per group ----
        float nm[2][2];
        #pragma unroll
        for (int grp = 0; grp < 2; grp++) {
            float tmax0 = -1e30f, tmax1 = -1e30f;
            #pragma unroll
            for (int nt = 0; nt < 8; nt++) {
                tmax0 = fmaxf(tmax0, fmaxf(sacc[grp][nt][0], sacc[grp][nt][1]));
                tmax1 = fmaxf(tmax1, fmaxf(sacc[grp][nt][2], sacc[grp][nt][3]));
            }
            tmax0 = fmaxf(tmax0, __shfl_xor_sync(0xffffffffu, tmax0, 1));
            tmax0 = fmaxf(tmax0, __shfl_xor_sync(0xffffffffu, tmax0, 2));
            tmax1 = fmaxf(tmax1, __shfl_xor_sync(0xffffffffu, tmax1, 1));
            tmax1 = fmaxf(tmax1, __shfl_xor_sync(0xffffffffu, tmax1, 2));
            const float nm0 = fmaxf(m[grp][0], tmax0);
            const float nm1 = fmaxf(m[grp][1], tmax1);
            const float corr0 = __expf(m[grp][0] - nm0);
            const float corr1 = __expf(m[grp][1] - nm1);
            l[grp][0] *= corr0;
            l[grp][1] *= corr1;
            #pragma unroll
            for (int nt = 0; nt < 8; nt++) {
                oacc[grp][nt][0] *= corr0; oacc[grp][nt][1] *= corr0;
                oacc[grp][nt][2] *= corr1; oacc[grp][nt][3] *= corr1;
            }
            m[grp][0] = nm0; m[grp][1] = nm1;
            nm[grp][0] = nm0; nm[grp][1] = nm1;
        }

        // ---- PV: exp in C layout == A layout, pack f16x2, mma. No shfl. ----
        const uint32_t vT = sV[cur] + foff;
        #pragma unroll
        for (int ks2 = 0; ks2 < 4; ks2++) {     // 16 keys per step
            uint32_t bfr[8][2];
            #pragma unroll
            for (int p = 0; p < 4; p++) {
                uint32_t r4[4];
                ldsm4(r4, vT + (uint32_t)(p * 16 * AST) * 2u + (uint32_t)ks2 * 32u);
                bfr[2 * p][0] = r4[0]; bfr[2 * p][1] = r4[2];
                bfr[2 * p + 1][0] = r4[1]; bfr[2 * p + 1][1] = r4[3];
            }
            #pragma unroll
            for (int grp = 0; grp < 2; grp++) {
                const int nt0 = 2 * ks2, nt1 = 2 * ks2 + 1;
                const float p00 = __expf(sacc[grp][nt0][0] - nm[grp][0]);
                const float p01 = __expf(sacc[grp][nt0][1] - nm[grp][0]);
                const float p02 = __expf(sacc[grp][nt0][2] - nm[grp][1]);
                const float p03 = __expf(sacc[grp][nt0][3] - nm[grp][1]);
                const float p10 = __expf(sacc[grp][nt1][0] - nm[grp][0]);
                const float p11 = __expf(sacc[grp][nt1][1] - nm[grp][0]);
                const float p12 = __expf(sacc[grp][nt1][2] - nm[grp][1]);
                const float p13 = __expf(sacc[grp][nt1][3] - nm[grp][1]);
                l[grp][0] += (p00 + p01) + (p10 + p11);
                l[grp][1] += (p02 + p03) + (p12 + p13);
                uint32_t af[4];
                af[0] = pack_h2(p00, p01);
                af[1] = pack_h2(p02, p03);
                af[2] = pack_h2(p10, p11);
                af[3] = pack_h2(p12, p13);
                #pragma unroll
                for (int nt = 0; nt < 8; nt++)
                    mma_f16(oacc[grp][nt], af, bfr[nt]);
            }
        }
        __syncthreads();
    }

    // Epilogue: O as fp16 head-split (consumed by gemm_o).
    #pragma unroll
    for (int grp = 0; grp < 2; grp++) {
        float la = l[grp][0], lb = l[grp][1];
        la += __shfl_xor_sync(0xffffffffu, la, 1);
        la += __shfl_xor_sync(0xffffffffu, la, 2);
        lb += __shfl_xor_sync(0xffffffffu, lb, 1);
        lb += __shfl_xor_sync(0xffffffffu, lb, 2);
        const float inv0 = 1.f / la;
        const float inv1 = 1.f / lb;
        const int qr0 = qt * QT + wid * 32 + grp * 16 + g;
        const int qr1 = qr0 + 8;
        #pragma unroll
        for (int nt = 0; nt < 8; nt++) {
            const int d = nt * 8 + 2 * tig;
            const size_t off0 = headoff + (size_t)qr0 * DK + d;
            const size_t off1 = headoff + (size_t)qr1 * DK + d;
            *(__half2*)&g_O16[off0] =
                __floats2half2_rn(oacc[grp][nt][0] * inv0, oacc[grp][nt][1] * inv0);
            *(__half2*)&g_O16[off1] =
                __floats2half2_rn(oacc[grp][nt][2] * inv1, oacc[grp][nt][3] * inv1);
        }
    }
}

// ---------------------------------------------------------------------------
extern "C" void kernel_launch(void* const* d_in, const int* in_sizes, int n_in,
                              void* d_out, int out_size)
{
    const float* q  = (const float*)d_in[0];
    const float* k  = (const float*)d_in[1];
    const float* v  = (const float*)d_in[2];
    const float* Wq = (const float*)d_in[3];
    const float* Wk = (const float*)d_in[4];
    const float* Wv = (const float*)d_in[5];
    const float* Wo = (const float*)d_in[6];
    float* out = (float*)d_out;

    void *pQ, *pK, *pVt;
    cudaGetSymbolAddress(&pQ, g_Q16);
    cudaGetSymbolAddress(&pK, g_K16);
    cudaGetSymbolAddress(&pVt, g_Vt16);

    cudaFuncSetAttribute(gemm_qkv, cudaFuncAttributeMaxDynamicSharedMemorySize, GSMEM);
    cudaFuncSetAttribute(gemm_o, cudaFuncAttributeMaxDynamicSharedMemorySize, GSMEM);
    cudaFuncSetAttribute(attn_mma, cudaFuncAttributeMaxDynamicSharedMemorySize, ASMEM);

    // Pre-pass
    dim3 rgrid(NBIG4 / 256, 7);
    cvt_all<<<rgrid, 256>>>(
        (const float4*)q, (const float4*)k, (const float4*)v,
        (const float4*)Wq, (const float4*)Wk, (const float4*)Wv, (const float4*)Wo);

    // Fused Q/K/V projections
    dim3 qkv_grid(DD / 128, MM / 128, 3);   // (8, 64, 3)
    gemm_qkv<<<qkv_grid, 128, GSMEM>>>();

    // Attention
    dim3 attn_grid(SS / QT, HH, BB);        // (16, 16, 4)
    attn_mma<<<attn_grid, 128, ASMEM>>>((const __half*)pQ, (const __half*)pK,
                                        (const __half*)pVt);

    // Output projection
    dim3 o_grid(DD / 128, MM / 128);        // (8, 64)
    gemm_o<<<o_grid, 128, GSMEM>>>(out);
}